// round 10
// baseline (speedup 1.0000x reference)
#include <cuda_runtime.h>
#include <cuda_bf16.h>

// P1 FEM evaluation on a structured 17x17 grid over [0,1]^2.
// Direct cell lookup replaces the reference's 512-triangle scan.
//
// Bitwise-faithful DECISION logic vs the JAX reference (validated R4-R9):
//  - x*16 is an exact exponent shift; dx = ux - floor(ux), dy = uy - floor(uy)
//    and e = dy - dx are EXACT in fp32.
//  - The reference's 6 triangle conditions collapse exactly to one test:
//      up = e > -TOL  (upper overrides lower on the shared diagonal /
//      sub-TOL tie band, matching the reference scan order)
//  - TOL = 1e-10 is below fp32 ulp on interior grid lines -> those points
//    fail every strict bbox test in the reference -> output 0 (`dead`).
//    x==0 / y==0 edges survive (bbox lower bound -1e-10 is representable).
//  Value arithmetic uses an FMA form (different rounding than the reference
//  matmul, but decisions are exact; rel_err ~1e-7 << 1e-3 threshold).
//
// R10: combine R8's front-batched MLP=4 (fastest measured, 9.28us ncu) with
// R9's 7-blocks/SM single wave:
//  - all 4 LDG.128 issued before any eval (MLP_p1 = 4)
//  - store r0 before computing r1 -> peak live ~34 regs
//  - __launch_bounds__(256,7): 1024 blocks <= 148*7=1036 resident -> no tail
//  - shorter eval chain: shared e = dy-dx, FMA-form interpolation

static constexpr float TOLF = 1e-10f;

__device__ __forceinline__ float eval_point(float X, float Y,
                                            const float4* __restrict__ wq) {
    float ux = X * 16.0f;              // exact (power-of-2 scale)
    float uy = Y * 16.0f;
    float fx = floorf(ux);
    float fy = floorf(uy);
    // Interior grid line -> reference's strict bbox test fails everywhere.
    bool dead = ((ux == fx) && (fx != 0.0f)) || ((uy == fy) && (fy != 0.0f));

    float dx = ux - fx;                // exact
    float dy = uy - fy;                // exact
    float e  = dy - dx;                // exact

    int cell = (int)fmaf(fx, 16.0f, fy);   // i*16 + j, exact in fp32
    float4 q = wq[cell];               // (w00, w01, w10, w11) - one LDS.128

    bool up = e > -TOLF;               // upper triangle wins

    // val = w00 + s*(wa - w00) + t*(wb - w00)
    float s  = up ? dx  : -e;          // upper: dx      ; lower: dx-dy
    float t  = up ? e   : dy;          // upper: dy-dx   ; lower: dy
    float wa = up ? q.w : q.z;         // upper: w11     ; lower: w10
    float wb = up ? q.y : q.w;         // upper: w01     ; lower: w11
    float val = fmaf(s, wa - q.x, fmaf(t, wb - q.x, q.x));

    return dead ? 0.0f : val;
}

__global__ void __launch_bounds__(256, 7)
p1_eval_kernel(const float4* __restrict__ x4,
               const float*  __restrict__ w,
               float4*       __restrict__ out4) {
    // Packed per-cell weight table: wq[i*16+j] = (w00, w01, w10, w11).
    __shared__ float4 wq[256];
    {
        int t = threadIdx.x;           // t = i*16 + j, i,j in [0,16)
        int v = (t >> 4) * 17 + (t & 15);
        wq[t] = make_float4(w[v], w[v + 1], w[v + 17], w[v + 18]);
    }
    __syncthreads();

    // Each thread: 8 points = 4 input float4, 2 output float4.
    int o0 = blockIdx.x * 512 + threadIdx.x;   // output float4 index
    int o1 = o0 + 256;

    // Front-batched loads: 4 independent LDG.128 in flight (MLP_p1 = 4).
    float4 a0 = x4[2 * o0];
    float4 a1 = x4[2 * o0 + 1];
    float4 b0 = x4[2 * o1];
    float4 b1 = x4[2 * o1 + 1];

    // Eval + store first half before second half (shrinks live ranges
    // so ptxas can meet the 36-reg / 7-blocks-per-SM budget).
    float4 r0;
    r0.x = eval_point(a0.x, a0.y, wq);
    r0.y = eval_point(a0.z, a0.w, wq);
    r0.z = eval_point(a1.x, a1.y, wq);
    r0.w = eval_point(a1.z, a1.w, wq);
    out4[o0] = r0;

    float4 r1;
    r1.x = eval_point(b0.x, b0.y, wq);
    r1.y = eval_point(b0.z, b0.w, wq);
    r1.z = eval_point(b1.x, b1.y, wq);
    r1.w = eval_point(b1.z, b1.w, wq);
    out4[o1] = r1;
}

extern "C" void kernel_launch(void* const* d_in, const int* in_sizes, int n_in,
                              void* d_out, int out_size) {
    // Identify inputs by element count: x = largest (4,194,304 floats),
    // weight = 289 floats.
    const float* x = nullptr;
    const float* w = nullptr;
    int max_sz = -1;
    for (int k = 0; k < n_in; k++) {
        if (in_sizes[k] == 289) w = (const float*)d_in[k];
        if (in_sizes[k] > max_sz) { max_sz = in_sizes[k]; x = (const float*)d_in[k]; }
    }

    // 2,097,152 points -> 524,288 output float4 -> 1024 blocks x 256 threads x 2.
    p1_eval_kernel<<<1024, 256>>>((const float4*)x, w, (float4*)d_out);
}

// round 11
// speedup vs baseline: 1.0061x; 1.0061x over previous
#include <cuda_runtime.h>
#include <cuda_bf16.h>

// P1 FEM evaluation on a structured 17x17 grid over [0,1]^2.
// Direct cell lookup replaces the reference's 512-triangle scan.
//
// Bitwise-faithful DECISION logic vs the JAX reference (validated R4-R10):
//  - x*16 is an exact exponent shift; dx = ux - floor(ux), dy = uy - floor(uy)
//    and e = dy - dx are EXACT in fp32.
//  - The reference's 6 triangle conditions collapse exactly to one test:
//      up = e > -TOL  (upper overrides lower on the shared diagonal /
//      sub-TOL tie band, matching the reference scan order)
//  - TOL = 1e-10 is below fp32 ulp on interior grid lines -> those points
//    fail every strict bbox test in the reference -> output 0 (`dead`).
//    x==0 / y==0 edges survive (bbox lower bound -1e-10 is representable).
//  Value arithmetic: per-triangle affine form val = a + b*dx + c*dy with
//  b,c precomputed weight differences -- few-ulp rounding difference vs the
//  reference (tolerance 1e-3; measured ~1e-7 in prior rounds).
//
// R11 (diagnosis: ILP-starved; R8 @39regs beat R9/R10 @32regs):
//  - 16 points/thread, 512 blocks, __launch_bounds__(256,4) (<=64 regs):
//    8 front-batched LDG.128 (MLP=8) + 16 independent evals for ILP;
//    512 <= 148*4 resident -> single wave, no tail
//  - 512-entry per-TRIANGLE coeff table (8 KB): post-LDS chain is just
//    2 FMAs; index 2*cell+up computed fully in FP (exact ints <= 511)

static constexpr float TOLF = 1e-10f;

__device__ __forceinline__ float eval_point(float X, float Y,
                                            const float4* __restrict__ tab) {
    float ux = X * 16.0f;              // exact (power-of-2 scale)
    float uy = Y * 16.0f;
    float fx = floorf(ux);
    float fy = floorf(uy);
    // Interior grid line -> reference's strict bbox test fails everywhere.
    bool dead = ((ux == fx) && (fx != 0.0f)) || ((uy == fy) && (fy != 0.0f));

    float dx = ux - fx;                // exact
    float dy = uy - fy;                // exact
    float e  = dy - dx;                // exact

    float upf  = (e > -TOLF) ? 1.0f : 0.0f;            // upper triangle wins
    float idxf = fmaf(fx, 32.0f, fmaf(fy, 2.0f, upf)); // 2*(i*16+j)+up, exact
    int   idx  = (int)idxf;

    float4 q = tab[idx];               // (a, b, c, pad) - one LDS.128
    float val = fmaf(q.y, dx, fmaf(q.z, dy, q.x));

    return dead ? 0.0f : val;
}

__global__ void __launch_bounds__(256, 4)
p1_eval_kernel(const float4* __restrict__ x4,
               const float*  __restrict__ w,
               float4*       __restrict__ out4) {
    // Per-triangle affine coefficients: tab[2*cell+0] = lower, +1 = upper.
    __shared__ float4 tab[512];
    {
        int t = threadIdx.x;           // cell = i*16 + j
        int v = (t >> 4) * 17 + (t & 15);
        float w00 = w[v], w01 = w[v + 1], w10 = w[v + 17], w11 = w[v + 18];
        // lower (v00,v10,v11): val = w00 + dx*(w10-w00) + dy*(w11-w10)
        tab[2 * t]     = make_float4(w00, w10 - w00, w11 - w10, 0.0f);
        // upper (v00,v11,v01): val = w00 + dx*(w11-w01) + dy*(w01-w00)
        tab[2 * t + 1] = make_float4(w00, w11 - w01, w01 - w00, 0.0f);
    }
    __syncthreads();

    // Each thread: 16 points = 8 input float4 (front-batched), 4 output float4.
    int ob = blockIdx.x * 1024 + threadIdx.x;

    float4 a[8];
    #pragma unroll
    for (int k = 0; k < 4; k++) {
        int o = ob + k * 256;
        a[2 * k]     = x4[2 * o];
        a[2 * k + 1] = x4[2 * o + 1];
    }

    #pragma unroll
    for (int k = 0; k < 4; k++) {
        float4 r;
        r.x = eval_point(a[2 * k].x,     a[2 * k].y,     tab);
        r.y = eval_point(a[2 * k].z,     a[2 * k].w,     tab);
        r.z = eval_point(a[2 * k + 1].x, a[2 * k + 1].y, tab);
        r.w = eval_point(a[2 * k + 1].z, a[2 * k + 1].w, tab);
        out4[ob + k * 256] = r;        // store per group -> frees registers
    }
}

extern "C" void kernel_launch(void* const* d_in, const int* in_sizes, int n_in,
                              void* d_out, int out_size) {
    // Identify inputs by element count: x = largest (4,194,304 floats),
    // weight = 289 floats.
    const float* x = nullptr;
    const float* w = nullptr;
    int max_sz = -1;
    for (int k = 0; k < n_in; k++) {
        if (in_sizes[k] == 289) w = (const float*)d_in[k];
        if (in_sizes[k] > max_sz) { max_sz = in_sizes[k]; x = (const float*)d_in[k]; }
    }

    // 2,097,152 points -> 524,288 output float4
    //   = 512 blocks x 256 threads x 4 float4.
    p1_eval_kernel<<<512, 256>>>((const float4*)x, w, (float4*)d_out);
}

// round 12
// speedup vs baseline: 1.0249x; 1.0187x over previous
#include <cuda_runtime.h>
#include <cuda_bf16.h>

// P1 FEM evaluation on a structured 17x17 grid over [0,1]^2.
// Direct cell lookup replaces the reference's 512-triangle scan.
//
// Bitwise-faithful DECISION logic vs the JAX reference (validated R4-R11):
//  - x*16 is an exact exponent shift; dx = ux - floor(ux), dy = uy - floor(uy)
//    and e = dy - dx are EXACT in fp32.
//  - Reference's 6 triangle conditions collapse to: upper wins iff e > -TOL.
//  - ALGEBRAIC FOLD (R12): upper_val - lower_val = -e*g with
//    g = w00+w11-w01-w10 per cell, so
//      val = w00 + (w10-w00)*dx + (w11-w10)*dy - max(e,0)*g
//    max(e,0) matches the scan-order choice exactly for e>0 and e<=-TOL;
//    in the tie band e in (-TOL, 0] the difference is <= TOL*|g| ~ 4e-10,
//    far below the 1e-3 tolerance (value path already deviates ~7e-8).
//  - TOL = 1e-10 is below fp32 ulp on interior grid lines -> those points
//    fail every strict bbox test in the reference -> output 0 (`dead`).
//    x==0 / y==0 edges survive (bbox lower bound -1e-10 is representable).
//
// R12 config = R8's best-measured shape (1024 blocks x 256 thr, 8 pts/thread,
// front-batched MLP=4, natural regs) with ~5 fewer instructions per point:
// no up-select, no weight FSELs, post-LDS chain = 3 FMA + 1 FMAX.

static constexpr float TOLF = 1e-10f;

__device__ __forceinline__ float eval_point(float X, float Y,
                                            const float4* __restrict__ tab) {
    float ux = X * 16.0f;              // exact (power-of-2 scale)
    float uy = Y * 16.0f;
    float fx = floorf(ux);
    float fy = floorf(uy);

    float dx = ux - fx;                // exact
    float dy = uy - fy;                // exact
    float e  = dy - dx;                // exact

    // Interior grid line -> reference's strict bbox test fails everywhere.
    bool dead = ((dx == 0.0f) && (ux != 0.0f)) || ((dy == 0.0f) && (uy != 0.0f));

    int cell = (int)fmaf(fx, 16.0f, fy);   // i*16 + j, exact in fp32
    float4 q = tab[cell];              // (w00, b, c, g) - one LDS.128

    float emax = fmaxf(e, 0.0f);
    float val  = fmaf(q.y, dx, fmaf(q.z, dy, q.x));
    val = fmaf(-emax, q.w, val);

    return dead ? 0.0f : val;
}

__global__ void __launch_bounds__(256)
p1_eval_kernel(const float4* __restrict__ x4,
               const float*  __restrict__ w,
               float4*       __restrict__ out4) {
    // Per-cell fold coefficients: (w00, w10-w00, w11-w10, w00+w11-w01-w10).
    __shared__ float4 tab[256];
    {
        int t = threadIdx.x;           // cell = i*16 + j
        int v = (t >> 4) * 17 + (t & 15);
        float w00 = w[v], w01 = w[v + 1], w10 = w[v + 17], w11 = w[v + 18];
        tab[t] = make_float4(w00, w10 - w00, w11 - w10,
                             (w00 + w11) - (w01 + w10));
    }
    __syncthreads();

    // Each thread: 8 points = 4 input float4 (front-batched), 2 output float4.
    int o0 = blockIdx.x * 512 + threadIdx.x;   // output float4 index
    int o1 = o0 + 256;

    float4 a0 = x4[2 * o0];
    float4 a1 = x4[2 * o0 + 1];
    float4 b0 = x4[2 * o1];
    float4 b1 = x4[2 * o1 + 1];

    float4 r0, r1;
    r0.x = eval_point(a0.x, a0.y, tab);
    r0.y = eval_point(a0.z, a0.w, tab);
    r0.z = eval_point(a1.x, a1.y, tab);
    r0.w = eval_point(a1.z, a1.w, tab);
    r1.x = eval_point(b0.x, b0.y, tab);
    r1.y = eval_point(b0.z, b0.w, tab);
    r1.z = eval_point(b1.x, b1.y, tab);
    r1.w = eval_point(b1.z, b1.w, tab);

    out4[o0] = r0;
    out4[o1] = r1;
}

extern "C" void kernel_launch(void* const* d_in, const int* in_sizes, int n_in,
                              void* d_out, int out_size) {
    // Identify inputs by element count: x = largest (4,194,304 floats),
    // weight = 289 floats.
    const float* x = nullptr;
    const float* w = nullptr;
    int max_sz = -1;
    for (int k = 0; k < n_in; k++) {
        if (in_sizes[k] == 289) w = (const float*)d_in[k];
        if (in_sizes[k] > max_sz) { max_sz = in_sizes[k]; x = (const float*)d_in[k]; }
    }

    // 2,097,152 points -> 524,288 output float4 -> 1024 blocks x 256 threads x 2.
    p1_eval_kernel<<<1024, 256>>>((const float4*)x, w, (float4*)d_out);
}